// round 2
// baseline (speedup 1.0000x reference)
#include <cuda_runtime.h>
#include <math.h>

#define NB 4
#define NCOIL 15
#define HH 320
#define WW 320
#define NF 32
#define KS 11
#define HP 342          // 320 + 2*11
#define NLUT 2048
#define LUT_MIN (-1.6f)
#define LUT_SPAN (3.2f)
#define LUT_SCALE ((float)(NLUT - 1) / LUT_SPAN)

// -------- scratch (device globals; no runtime allocation allowed) ----------
__device__ float2 g_upad[NB * HP * HP];            // ~3.7 MB
__device__ float  g_fuk[NB * NF * HP * HP];        // ~60 MB
__device__ float2 g_work[NB * NCOIL * HH * WW];    // ~49 MB
__device__ float  g_lut[NF * NLUT];
__device__ float2 g_tw[320];                       // W320^j = e^{-2pi i j/320}

// ---------------------------------------------------------------------------
__device__ __forceinline__ float2 cmulf(float2 a, float2 b) {
    return make_float2(fmaf(a.x, b.x, -(a.y * b.y)), fmaf(a.x, b.y, a.y * b.x));
}

template <int SIGN>
__device__ __forceinline__ float2 twd(const float2* tw, int idx) {
    float2 t = tw[idx];
    return make_float2(t.x, (SIGN < 0) ? t.y : -t.y);
}

// One radix-4 Stockham stage: total length 320 = n*s, n divisible by 4.
template <int SIGN, int n, int s>
__device__ __forceinline__ void stage4(const float2* __restrict__ src,
                                       float2* __restrict__ dst,
                                       const float2* tw, int t) {
    const int m = n / 4;
    const int stride = 320 / n;
    int p = t % m, q = t / m;        // m*s == 80 for all stages used
    float2 a0 = src[q + s * (p + 0 * m)];
    float2 a1 = src[q + s * (p + 1 * m)];
    float2 a2 = src[q + s * (p + 2 * m)];
    float2 a3 = src[q + s * (p + 3 * m)];
    float2 t0 = make_float2(a0.x + a2.x, a0.y + a2.y);
    float2 t1 = make_float2(a0.x - a2.x, a0.y - a2.y);
    float2 t2 = make_float2(a1.x + a3.x, a1.y + a3.y);
    float2 t3 = make_float2(a1.x - a3.x, a1.y - a3.y);
    float2 it3 = make_float2(-t3.y, t3.x);          // i * t3
    float2 A0 = make_float2(t0.x + t2.x, t0.y + t2.y);
    float2 A2 = make_float2(t0.x - t2.x, t0.y - t2.y);
    float2 A1 = make_float2(t1.x + SIGN * it3.x, t1.y + SIGN * it3.y);
    float2 A3 = make_float2(t1.x - SIGN * it3.x, t1.y - SIGN * it3.y);
    dst[q + s * (4 * p + 0)] = A0;
    dst[q + s * (4 * p + 1)] = cmulf(A1, twd<SIGN>(tw, p * stride));
    dst[q + s * (4 * p + 2)] = cmulf(A2, twd<SIGN>(tw, 2 * p * stride));
    dst[q + s * (4 * p + 3)] = cmulf(A3, twd<SIGN>(tw, 3 * p * stride));
}

// 320-point Stockham FFT (radices 5,4,4,4). X,Y: smem buffers (len 320).
// t in [0,80). Result ends up in X. Caller must have synced X before call.
template <int SIGN>
__device__ void fft320(float2* X, float2* Y, const float2* tw, int t) {
    // stage 1: n=320, r=5, m=64, s=1
    if (t < 64) {
        int p = t;
        float2 a[5];
#pragma unroll
        for (int j = 0; j < 5; j++) a[j] = X[p + 64 * j];
#pragma unroll
        for (int k = 0; k < 5; k++) {
            float2 acc = a[0];
#pragma unroll
            for (int j = 1; j < 5; j++) {
                float2 w5 = twd<SIGN>(tw, 64 * ((j * k) % 5));
                float2 pr = cmulf(a[j], w5);
                acc.x += pr.x; acc.y += pr.y;
            }
            float2 wt = twd<SIGN>(tw, p * k);   // p*k <= 252 < 320
            Y[5 * p + k] = cmulf(acc, wt);
        }
    }
    __syncthreads();
    stage4<SIGN, 64, 5>(Y, X, tw, t);
    __syncthreads();
    stage4<SIGN, 16, 20>(X, Y, tw, t);
    __syncthreads();
    stage4<SIGN, 4, 80>(Y, X, tw, t);
    __syncthreads();
    // result in X
}

// ---------------------------- init kernels ---------------------------------
__global__ void k_tw() {
    int j = threadIdx.x;
    if (j < 320) {
        double th = -2.0 * 3.14159265358979323846 * (double)j / 320.0;
        g_tw[j] = make_float2((float)cos(th), (float)sin(th));
    }
}

__global__ void k_lut(const float* __restrict__ w, const float* __restrict__ mu,
                      const float* __restrict__ sigma) {
    int f = blockIdx.x;
    float inv2s2 = 1.0f / (2.0f * sigma[0] * sigma[0]);
    for (int t = threadIdx.x; t < NLUT; t += blockDim.x) {
        float x = LUT_MIN + LUT_SPAN * (float)t / (float)(NLUT - 1);
        float acc = 0.0f;
        for (int i = 0; i < 31; i++) {
            float d = x - mu[i];
            acc += w[f * 31 + i] * expf(-d * d * inv2s2);
        }
        g_lut[f * NLUT + t] = acc;
    }
}

__global__ void k_pad(const float* __restrict__ u) {
    int idx = blockIdx.x * blockDim.x + threadIdx.x;
    if (idx >= NB * HP * HP) return;
    int x = idx % HP, y = (idx / HP) % HP, n = idx / (HP * HP);
    int sy = y - 11; sy = (sy < 0) ? -sy : ((sy > 319) ? 638 - sy : sy);
    int sx = x - 11; sx = (sx < 0) ? -sx : ((sx > 319) ? 638 - sx : sx);
    g_upad[idx] = ((const float2*)u)[(n * HH + sy) * WW + sx];
}

// --------------------- forward conv (2ch -> 32) + RBF-LUT ------------------
// tile: 32 rows x 64 cols of output, one (n,f) per block-z, 256 threads,
// each thread computes 1x8 outputs.
__global__ void k_conv(const float* __restrict__ ck) {
    __shared__ float2 sIn[42 * 74];
    __shared__ float  sLut[NLUT];
    __shared__ float2 sK[121];
    int nf = blockIdx.z, n = nf >> 5, f = nf & 31;
    int y0 = blockIdx.y * 32, x0 = blockIdx.x * 64;
    int tid = threadIdx.x;
    for (int i = tid; i < NLUT; i += 256) sLut[i] = g_lut[f * NLUT + i];
    const float2* ck2 = (const float2*)ck;
    for (int i = tid; i < 121; i += 256) sK[i] = ck2[f * 121 + i];
    for (int i = tid; i < 42 * 74; i += 256) {
        int ly = i / 74, lx = i % 74;
        int gy = y0 + ly - 5, gx = x0 + lx - 5;
        float2 v = make_float2(0.f, 0.f);
        if ((unsigned)gy < (unsigned)HP && (unsigned)gx < (unsigned)HP)
            v = g_upad[(n * HP + gy) * HP + gx];
        sIn[i] = v;
    }
    __syncthreads();
    int ty = tid >> 3, tx8 = (tid & 7) * 8;
    float acc[8];
#pragma unroll
    for (int j = 0; j < 8; j++) acc[j] = 0.f;
    for (int ky = 0; ky < 11; ky++) {
        float2 v[18];
#pragma unroll
        for (int p = 0; p < 18; p++) v[p] = sIn[(ty + ky) * 74 + tx8 + p];
#pragma unroll
        for (int kx = 0; kx < 11; kx++) {
            float2 wv = sK[ky * 11 + kx];
#pragma unroll
            for (int j = 0; j < 8; j++) {
                acc[j] = fmaf(v[kx + j].x, wv.x, acc[j]);
                acc[j] = fmaf(v[kx + j].y, wv.y, acc[j]);
            }
        }
    }
    int y = y0 + ty;
    if (y < HP) {
        float* dst = &g_fuk[((n * NF + f) * HP + y) * HP];
#pragma unroll
        for (int j = 0; j < 8; j++) {
            int x = x0 + tx8 + j;
            if (x < HP) {
                float tpos = (acc[j] - LUT_MIN) * LUT_SCALE;
                tpos = fminf(fmaxf(tpos, 0.f), (float)(NLUT - 1) - 0.001f);
                int ii = (int)tpos;
                float fr = tpos - (float)ii;
                dst[x] = sLut[ii] + fr * (sLut[ii + 1] - sLut[ii]);
            }
        }
    }
}

// ----------------------------- FFT passes ----------------------------------
// pass 1: rows forward.  q = D*(u*cs); scale by 1/320 (full fwd ortho factor)
__global__ void k_fft_row_fwd(const float* __restrict__ u,
                              const float* __restrict__ cs) {
    __shared__ float2 sm[4][2][320];
    __shared__ float2 sTw[320];
    int tid = threadIdx.x;
    sTw[tid] = g_tw[tid];
    int g = tid / 80, t = tid % 80;
    int rowIdx = blockIdx.x * 4 + g;
    int r = rowIdx % HH, nc = rowIdx / HH;
    int n = nc / NCOIL;
    const float2* up = (const float2*)u + (n * HH + r) * WW;
    const float2* cp = (const float2*)cs + (nc * HH + r) * WW;
    float2* X = &sm[g][0][0];
    float2* Y = &sm[g][1][0];
    for (int x = t; x < 320; x += 80) {
        float2 q = cmulf(up[x], cp[x]);
        float sgn = ((r + x) & 1) ? -1.f : 1.f;
        X[x] = make_float2(sgn * q.x, sgn * q.y);
    }
    __syncthreads();
    fft320<-1>(X, Y, sTw, t);
    float2* dst = g_work + nc * (HH * WW) + r * WW;
    const float sc = 1.f / 320.f;
    for (int x = t; x < 320; x += 80)
        dst[x] = make_float2(X[x].x * sc, X[x].y * sc);
}

// pass 2: columns forward + S = m*(Q - D*f)
__global__ void k_fft_col_fwd(const float* __restrict__ fdat,
                              const float* __restrict__ mask) {
    __shared__ float2 sm[4][2][320];
    __shared__ float2 sTw[320];
    int tid = threadIdx.x;
    sTw[tid] = g_tw[tid];
    int blk = blockIdx.x;
    int nc = blk / 80, cb = (blk % 80) * 4;
    int n = nc / NCOIL;
    float2* base = g_work + nc * (HH * WW);
    for (int i = tid; i < 1280; i += 320) {
        int row = i >> 2, cc = i & 3;
        sm[cc][0][row] = base[row * WW + cb + cc];
    }
    __syncthreads();
    int g = tid / 80, t = tid % 80;
    fft320<-1>(&sm[g][0][0], &sm[g][1][0], sTw, t);
    const float2* f2 = (const float2*)fdat + nc * (HH * WW);
    for (int i = tid; i < 1280; i += 320) {
        int row = i >> 2, cc = i & 3;
        int col = cb + cc;
        float m = mask[n * (HH * WW) + row * WW + col];
        float2 fv = f2[row * WW + col];
        float sgn = ((row + col) & 1) ? -1.f : 1.f;
        float2 q = sm[cc][0][row];
        base[row * WW + col] =
            make_float2(m * (q.x - sgn * fv.x), m * (q.y - sgn * fv.y));
    }
}

// pass 3: rows inverse (conj twiddles), scale 1/320 (full inv ortho factor)
__global__ void k_fft_row_inv() {
    __shared__ float2 sm[4][2][320];
    __shared__ float2 sTw[320];
    int tid = threadIdx.x;
    sTw[tid] = g_tw[tid];
    int g = tid / 80, t = tid % 80;
    int rowIdx = blockIdx.x * 4 + g;
    int r = rowIdx % HH, nc = rowIdx / HH;
    float2* rowp = g_work + nc * (HH * WW) + r * WW;
    float2* X = &sm[g][0][0];
    float2* Y = &sm[g][1][0];
    for (int x = t; x < 320; x += 80) X[x] = rowp[x];
    __syncthreads();
    fft320<1>(X, Y, sTw, t);
    const float sc = 1.f / 320.f;
    for (int x = t; x < 320; x += 80)
        rowp[x] = make_float2(X[x].x * sc, X[x].y * sc);
}

// pass 4: columns inverse, then v -> D * v * conj(cs)  (per-coil contribution)
__global__ void k_fft_col_inv(const float* __restrict__ cs) {
    __shared__ float2 sm[4][2][320];
    __shared__ float2 sTw[320];
    int tid = threadIdx.x;
    sTw[tid] = g_tw[tid];
    int blk = blockIdx.x;
    int nc = blk / 80, cb = (blk % 80) * 4;
    float2* base = g_work + nc * (HH * WW);
    for (int i = tid; i < 1280; i += 320) {
        int row = i >> 2, cc = i & 3;
        sm[cc][0][row] = base[row * WW + cb + cc];
    }
    __syncthreads();
    int g = tid / 80, t = tid % 80;
    fft320<1>(&sm[g][0][0], &sm[g][1][0], sTw, t);
    const float2* c2 = (const float2*)cs + nc * (HH * WW);
    for (int i = tid; i < 1280; i += 320) {
        int row = i >> 2, cc = i & 3;
        int col = cb + cc;
        float2 v = sm[cc][0][row];
        float2 cv = c2[row * WW + col];
        float sgn = ((row + col) & 1) ? -1.f : 1.f;
        // sgn * v * conj(cv)
        float2 o;
        o.x = sgn * (v.x * cv.x + v.y * cv.y);
        o.y = sgn * (v.y * cv.x - v.x * cv.y);
        base[row * WW + col] = o;
    }
}

// --------------- adjoint conv + coil sum + final combine -------------------
// tile 32x32 output pixels, 256 threads, 1x4 outputs per thread.
__global__ void k_final(const float* __restrict__ u,
                        const float* __restrict__ ck,
                        const float* __restrict__ lamb,
                        float2* __restrict__ out) {
    __shared__ float  sT[42 * 42];
    __shared__ float2 sK[121];
    int n = blockIdx.z;
    int y0 = blockIdx.y * 32, x0 = blockIdx.x * 32;
    int tid = threadIdx.x;
    int ty = tid >> 3, tx4 = (tid & 7) * 4;
    float ar[4] = {0.f, 0.f, 0.f, 0.f};
    float ai[4] = {0.f, 0.f, 0.f, 0.f};
    const float2* ck2 = (const float2*)ck;
    for (int f = 0; f < NF; f++) {
        __syncthreads();
        for (int i = tid; i < 42 * 42; i += 256) {
            int ly = i / 42, lx = i % 42;
            sT[i] = g_fuk[((n * NF + f) * HP + (y0 + 6 + ly)) * HP + (x0 + 6 + lx)];
        }
        for (int i = tid; i < 121; i += 256) sK[i] = ck2[f * 121 + 120 - i];
        __syncthreads();
#pragma unroll
        for (int a = 0; a < 11; a++) {
            float v[14];
#pragma unroll
            for (int p = 0; p < 14; p++) v[p] = sT[(ty + a) * 42 + tx4 + p];
#pragma unroll
            for (int b = 0; b < 11; b++) {
                float2 wv = sK[a * 11 + b];
#pragma unroll
                for (int j = 0; j < 4; j++) {
                    ar[j] = fmaf(v[b + j], wv.x, ar[j]);
                    ai[j] = fmaf(v[b + j], wv.y, ai[j]);
                }
            }
        }
    }
    float lam = lamb[0];
#pragma unroll
    for (int j = 0; j < 4; j++) {
        int y = y0 + ty, x = x0 + tx4 + j;
        float2 du = make_float2(0.f, 0.f);
        for (int c = 0; c < NCOIL; c++) {
            float2 vv = g_work[((n * NCOIL + c) * HH + y) * WW + x];
            du.x += vv.x; du.y += vv.y;
        }
        float2 uu = ((const float2*)u)[(n * HH + y) * WW + x];
        float2 o;
        o.x = uu.x - ar[j] * (1.f / 32.f) - lam * du.x;
        o.y = uu.y - ai[j] * (1.f / 32.f) - lam * du.y;
        out[(n * HH + y) * WW + x] = o;
    }
}

// ---------------------------------------------------------------------------
extern "C" void kernel_launch(void* const* d_in, const int* in_sizes, int n_in,
                              void* d_out, int out_size) {
    const float* u_t   = (const float*)d_in[0];
    const float* fdat  = (const float*)d_in[1];
    const float* cs    = (const float*)d_in[2];
    const float* mask  = (const float*)d_in[3];
    const float* ck    = (const float*)d_in[4];
    const float* w     = (const float*)d_in[5];
    const float* mu    = (const float*)d_in[6];
    const float* sigma = (const float*)d_in[7];
    const float* lamb  = (const float*)d_in[8];
    float2* out = (float2*)d_out;

    k_tw<<<1, 320>>>();
    k_lut<<<NF, 256>>>(w, mu, sigma);
    k_pad<<<(NB * HP * HP + 255) / 256, 256>>>(u_t);
    k_conv<<<dim3(6, 11, NB * NF), 256>>>(ck);

    int nrows = NB * NCOIL * HH;          // 19200
    k_fft_row_fwd<<<nrows / 4, 320>>>(u_t, cs);
    k_fft_col_fwd<<<NB * NCOIL * 80, 320>>>(fdat, mask);
    k_fft_row_inv<<<nrows / 4, 320>>>();
    k_fft_col_inv<<<NB * NCOIL * 80, 320>>>(cs);

    k_final<<<dim3(10, 10, NB), 256>>>(u_t, ck, lamb, out);
}